// round 3
// baseline (speedup 1.0000x reference)
#include <cuda_runtime.h>

// =====================================================================
// Photonic circuit (6 wires, Fock cutoff 2) -> 64 probs + residual + LN.
//
// Each sample's 64-complex state is SPLIT across 2 threads on wire 0
// (bit 5 of the state index): thread h in {0,1} holds the 32 amplitudes
// with n_0 = h. Cross-thread gates (BS on wires (0,1), Disp on wire 0)
// use shfl.xor(1) butterflies. Everything else is thread-local with
// compile-time register indices.
//
// All var-derived gate coefficients are sample-independent: computed
// once per block into shared memory. Diagonal gate groups are merged:
//   D_A = Sq(v16..21) o Rot(v10..15)   (64-entry complex diag)
//   D_B = Rot(v32..37)
//   Kerr(v44..49): layer 2's is pure phase before |.|^2 -> dropped;
//   layer 1's is commuted through layer 2's first BS chain
//   (phi_i -> phi_i + a_i - a_{i+1}) and folded into layer 2's D_A.
// =====================================================================

#define FULLMASK 0xFFFFFFFFu

__device__ __forceinline__ float fast_sech(float r) {
    float e = __expf(r);
    return __fdividef(2.0f, e + __fdividef(1.0f, e));
}

// ---- local (within-thread) gates on the 32-complex half-state ----

template<int LO>
__device__ __forceinline__ void localBS(float* sr, float* si, float4 q) {
    const float c = q.x, esr = q.y, esi = q.z, c2 = q.w;
    const int HI = LO << 1;
#pragma unroll
    for (int p = 0; p < 8; ++p) {
        const int j00 = ((p & ~(LO - 1)) << 2) | (p & (LO - 1));
        const int j01 = j00 | LO, j10 = j00 | HI, j11 = j00 | HI | LO;
        float a01 = sr[j01], b01 = si[j01];
        float a10 = sr[j10], b10 = si[j10];
        sr[j01] = c * a01 + esr * a10 - esi * b10;
        si[j01] = c * b01 + esr * b10 + esi * a10;
        sr[j10] = c * a10 - esr * a01 - esi * b01;
        si[j10] = c * b10 - esr * b01 + esi * a01;
        sr[j11] *= c2; si[j11] *= c2;
    }
}

template<int M>
__device__ __forceinline__ void localDisp(float* sr, float* si, float4 m) {
#pragma unroll
    for (int p = 0; p < 16; ++p) {
        const int j0 = ((p & ~(M - 1)) << 1) | (p & (M - 1));
        const int j1 = j0 | M;
        float a0 = sr[j0], b0 = si[j0], a1 = sr[j1], b1 = si[j1];
        sr[j0] = m.x * a0 + m.y * a1;
        si[j0] = m.x * b0 + m.y * b1;
        sr[j1] = m.z * a0 + m.w * a1;
        si[j1] = m.z * b0 + m.w * b1;
    }
}

__device__ __forceinline__ void applyDiag(float* sr, float* si, const float2* __restrict__ D) {
#pragma unroll
    for (int j = 0; j < 32; ++j) {
        float2 d = D[j];
        float a = sr[j], b = si[j];
        sr[j] = a * d.x - b * d.y;
        si[j] = a * d.y + b * d.x;
    }
}

// ---- cross-thread gates ----

// BS on wires (0,1): global masks HI=32 (held as h), LO=16.
// h=0 thread owns j01 (local p|16); h=1 thread owns j10 (local p), j11 (local p|16).
__device__ __forceinline__ void crossBS(float* sr, float* si, float4 q, int h) {
    const float c = q.x, esi = q.z, c2 = q.w;
    const float e1 = h ? -q.y : q.y;
#pragma unroll
    for (int p = 0; p < 16; ++p) {
        float ar = h ? sr[p] : sr[p | 16];
        float ai = h ? si[p] : si[p | 16];
        float pr = __shfl_xor_sync(FULLMASK, ar, 1);
        float pi = __shfl_xor_sync(FULLMASK, ai, 1);
        float nr = c * ar + e1 * pr - esi * pi;
        float ni = c * ai + e1 * pi + esi * pr;
        if (h) {
            sr[p] = nr; si[p] = ni;
            sr[p | 16] *= c2; si[p | 16] *= c2;
        } else {
            sr[p | 16] = nr; si[p | 16] = ni;
        }
    }
}

// Disp on wire 0: mixes local j (h=0) with local j (h=1) for all 32 j.
__device__ __forceinline__ void crossDisp(float* sr, float* si, float4 m, int h) {
    const float a = h ? m.w : m.x;
    const float b = h ? m.z : m.y;
#pragma unroll
    for (int j = 0; j < 32; ++j) {
        float pr = __shfl_xor_sync(FULLMASK, sr[j], 1);
        float pi = __shfl_xor_sync(FULLMASK, si[j], 1);
        sr[j] = a * sr[j] + b * pr;
        si[j] = a * si[j] + b * pi;
    }
}

// ---- encoding: product-state expansion on the local half-state ----

template<int W>   // wires 1..5, local mask 1<<(5-W)
__device__ __forceinline__ void expandL(float* sr, float* si, float f0, float f1r, float f1i) {
    const int M = 1 << (5 - W);
#pragma unroll
    for (int t = 0; t < (1 << (W - 1)); ++t) {
        const int j = t << (6 - W);
        float a = sr[j], b = si[j];
        sr[j | M] = a * f1r - b * f1i;
        si[j | M] = a * f1i + b * f1r;
        sr[j] = a * f0;
        si[j] = b * f0;
    }
}

__device__ __forceinline__ void wire_factors(const float* __restrict__ xp, int w,
                                             float& f0, float& f1r, float& f1i) {
    float r1   = xp[2 * w];
    float dr   = xp[28 + 2 * w];
    float dphi = xp[29 + 2 * w];
    float kerr = xp[40 + w];
    float r2   = xp[46 + 2 * w];
    float rot2 = xp[58 + w];

    float sech1 = fast_sech(r1);
    float d01   = sqrtf(sech1);
    float pref  = __expf(-0.5f * dr * dr);
    float sech2 = fast_sech(r2);
    float d02   = sqrtf(sech2);
    float d12   = sech2 * d02;

    float base = d01 * pref;
    f0 = base * d02;
    float A = base * d12 * dr;
    float sA, cA;
    __sincosf(dphi + kerr + rot2, &sA, &cA);
    f1r = A * cA;
    f1i = A * sA;
}

// one variational layer on the half-state
__device__ __forceinline__ void apply_layer(float* sr, float* si,
                                            const float2* __restrict__ DA,
                                            const float2* __restrict__ DB,
                                            const float4* __restrict__ BS1,
                                            const float4* __restrict__ BS2,
                                            const float4* __restrict__ DSP,
                                            int h) {
    crossBS(sr, si, BS1[0], h);
    localBS<8>(sr, si, BS1[1]);
    localBS<4>(sr, si, BS1[2]);
    localBS<2>(sr, si, BS1[3]);
    localBS<1>(sr, si, BS1[4]);
    applyDiag(sr, si, DA + h * 32);
    crossBS(sr, si, BS2[0], h);
    localBS<8>(sr, si, BS2[1]);
    localBS<4>(sr, si, BS2[2]);
    localBS<2>(sr, si, BS2[3]);
    localBS<1>(sr, si, BS2[4]);
    applyDiag(sr, si, DB + h * 32);
    crossDisp(sr, si, DSP[0], h);
    localDisp<16>(sr, si, DSP[1]);
    localDisp<8 >(sr, si, DSP[2]);
    localDisp<4 >(sr, si, DSP[3]);
    localDisp<2 >(sr, si, DSP[4]);
    localDisp<1 >(sr, si, DSP[5]);
}

#define THREADS 256

extern "C" __global__ void __launch_bounds__(THREADS, 2)
ffblock_kernel(const float* __restrict__ x, const float* __restrict__ var,
               const float* __restrict__ gamma, const float* __restrict__ beta,
               float* __restrict__ out, int nsamp)
{
    __shared__ float2 sDA[2][64];
    __shared__ float2 sDB[2][64];
    __shared__ float4 sBS1[2][5];
    __shared__ float4 sBS2[2][5];
    __shared__ float4 sDSP[2][6];

    const int tid = threadIdx.x;

    // ---- per-block coefficient setup (var is shared by all samples) ----
    if (tid < 64) {
        const int j = tid;
        for (int l = 0; l < 2; ++l) {
            const float* v = var + 50 * l;
            float mag = 1.0f, phA = 0.0f, phB = 0.0f;
            for (int w = 0; w < 6; ++w) {
                int n = (j >> (5 - w)) & 1;
                float sh = fast_sech(v[16 + w]);
                float d0 = sqrtf(sh);
                mag *= n ? sh * d0 : d0;
                if (n) {
                    phA += v[10 + w] + (l ? var[44 + w] : 0.0f);  // fold layer-0 Kerr into layer-1 D_A
                    phB += v[32 + w];
                }
            }
            float s_, c_;
            __sincosf(phA, &s_, &c_);
            sDA[l][j] = make_float2(mag * c_, mag * s_);
            __sincosf(phB, &s_, &c_);
            sDB[l][j] = make_float2(c_, s_);
        }
    } else if (tid < 84) {
        int k = tid - 64;
        int isB2 = (k >= 10);
        if (isB2) k -= 10;
        int l = k / 5, i = k % 5;
        const float* v = var + 50 * l;
        float th, ph;
        if (isB2) { th = v[22 + 2 * i]; ph = v[23 + 2 * i]; }
        else {
            th = v[2 * i]; ph = v[2 * i + 1];
            if (l == 1) ph += var[44 + i] - var[44 + i + 1];  // Kerr phases commuted through BS
        }
        float st, ct, sp, cp;
        __sincosf(th, &st, &ct);
        __sincosf(ph, &sp, &cp);
        float4 q = make_float4(ct, st * cp, st * sp, 1.0f - 2.0f * st * st);
        if (isB2) sBS2[l][i] = q; else sBS1[l][i] = q;
    } else if (tid < 96) {
        int k = tid - 84;
        int l = k / 6, w = k % 6;
        const float* v = var + 50 * l;
        float r = v[38 + w];
        float pf = __expf(-0.5f * r * r);
        sDSP[l][w] = make_float4(pf, -pf * r, pf * r, pf * (1.0f - r * r));
    }
    __syncthreads();

    // ---- per-sample work: 2 threads per sample ----
    int gid = blockIdx.x * THREADS + tid;
    int sample = gid >> 1;
    if (sample >= nsamp) sample = nsamp - 1;   // pair-safe clamp (duplicate work)
    const int h = gid & 1;
    const float* xp = x + (size_t)sample * 64;

    float sr[32], si[32];
    {
        float f0, f1r, f1i;
        wire_factors(xp, 0, f0, f1r, f1i);
        sr[0] = h ? f1r : f0;
        si[0] = h ? f1i : 0.0f;
        wire_factors(xp, 1, f0, f1r, f1i); expandL<1>(sr, si, f0, f1r, f1i);
        wire_factors(xp, 2, f0, f1r, f1i); expandL<2>(sr, si, f0, f1r, f1i);
        wire_factors(xp, 3, f0, f1r, f1i); expandL<3>(sr, si, f0, f1r, f1i);
        wire_factors(xp, 4, f0, f1r, f1i); expandL<4>(sr, si, f0, f1r, f1i);
        wire_factors(xp, 5, f0, f1r, f1i); expandL<5>(sr, si, f0, f1r, f1i);
    }

    apply_layer(sr, si, sDA[0], sDB[0], sBS1[0], sBS2[0], sDSP[0], h);
    apply_layer(sr, si, sDA[1], sDB[1], sBS1[1], sBS2[1], sDSP[1], h);
    // (layer-2 Kerr rotations are pure phase before |.|^2 -> omitted)

    // ---- probs + residual + LayerNorm ----
    float sum = 0.0f, sumsq = 0.0f;
    const float* xr = xp + h * 32;
#pragma unroll
    for (int j = 0; j < 32; ++j) {
        float p = sr[j] * sr[j] + si[j] * si[j];
        float y = p + xr[j];
        sr[j] = y;
        sum += y;
        sumsq += y * y;
    }
    sum   += __shfl_xor_sync(FULLMASK, sum, 1);
    sumsq += __shfl_xor_sync(FULLMASK, sumsq, 1);
    float mean = sum * (1.0f / 64.0f);
    float varr = sumsq * (1.0f / 64.0f) - mean * mean;
    float inv = rsqrtf(varr + 1e-5f);

    float* op = out + (size_t)sample * 64 + h * 32;
    const float* gp = gamma + h * 32;
    const float* bp = beta + h * 32;
#pragma unroll
    for (int j = 0; j < 32; ++j) {
        op[j] = (sr[j] - mean) * inv * gp[j] + bp[j];
    }
}

extern "C" void kernel_launch(void* const* d_in, const int* in_sizes, int n_in,
                              void* d_out, int out_size) {
    const float* x     = (const float*)d_in[0];
    const float* var   = (const float*)d_in[1];
    const float* gamma = (const float*)d_in[2];
    const float* beta  = (const float*)d_in[3];
    float* out = (float*)d_out;

    int nsamp = in_sizes[0] / 64;
    int blocks = (2 * nsamp + THREADS - 1) / THREADS;
    ffblock_kernel<<<blocks, THREADS>>>(x, var, gamma, beta, out, nsamp);
}

// round 11
// speedup vs baseline: 2.1401x; 2.1401x over previous
#include <cuda_runtime.h>
#include <cuda_bf16.h>
#include <cstdint>

#define FULLMASK 0xFFFFFFFFu

// Real-embedded variational map M[128][128] (interleaved: col 2n=Re, 2n+1=Im):
// D[s,c] = sum_k F[s,k] * M[c,k]
__device__ float Wg[16384];

// ---------------- baseline tensor-core helpers (compute_103-legal) ----------------
__device__ __forceinline__ uint32_t smem_u32(const void* p) {
    uint32_t a;
    asm("{ .reg .u64 t; cvta.to.shared.u64 t, %1; cvt.u32.u64 %0, t; }" : "=r"(a) : "l"(p));
    return a;
}
__device__ __forceinline__ void ldsm4(uint32_t* r, uint32_t addr) {
    asm volatile("ldmatrix.sync.aligned.m8n8.x4.shared.b16 {%0,%1,%2,%3}, [%4];"
                 : "=r"(r[0]), "=r"(r[1]), "=r"(r[2]), "=r"(r[3]) : "r"(addr));
}
__device__ __forceinline__ void mma16816(float* d, const uint32_t* a, const uint32_t* b) {
    asm volatile("mma.sync.aligned.m16n8k16.row.col.f32.bf16.bf16.f32 "
                 "{%0,%1,%2,%3}, {%4,%5,%6,%7}, {%8,%9}, {%0,%1,%2,%3};"
                 : "+f"(d[0]), "+f"(d[1]), "+f"(d[2]), "+f"(d[3])
                 : "r"(a[0]), "r"(a[1]), "r"(a[2]), "r"(a[3]), "r"(b[0]), "r"(b[1]));
}

// ---------------- gate math (build_w only; proven in round 2) ----------------
__device__ __forceinline__ float fast_sech(float r) {
    float e = __expf(r);
    return __fdividef(2.0f, e + __fdividef(1.0f, e));
}
template<int LO>
__device__ __forceinline__ void localBS(float* sr, float* si, float4 q) {
    const float c = q.x, esr = q.y, esi = q.z, c2 = q.w;
    const int HI = LO << 1;
#pragma unroll
    for (int p = 0; p < 8; ++p) {
        const int j00 = ((p & ~(LO - 1)) << 2) | (p & (LO - 1));
        const int j01 = j00 | LO, j10 = j00 | HI, j11 = j00 | HI | LO;
        float a01 = sr[j01], b01 = si[j01], a10 = sr[j10], b10 = si[j10];
        sr[j01] = c * a01 + esr * a10 - esi * b10;
        si[j01] = c * b01 + esr * b10 + esi * a10;
        sr[j10] = c * a10 - esr * a01 - esi * b01;
        si[j10] = c * b10 - esr * b01 + esi * a01;
        sr[j11] *= c2; si[j11] *= c2;
    }
}
template<int M>
__device__ __forceinline__ void localDisp(float* sr, float* si, float4 m) {
#pragma unroll
    for (int p = 0; p < 16; ++p) {
        const int j0 = ((p & ~(M - 1)) << 1) | (p & (M - 1));
        const int j1 = j0 | M;
        float a0 = sr[j0], b0 = si[j0], a1 = sr[j1], b1 = si[j1];
        sr[j0] = m.x * a0 + m.y * a1;  si[j0] = m.x * b0 + m.y * b1;
        sr[j1] = m.z * a0 + m.w * a1;  si[j1] = m.z * b0 + m.w * b1;
    }
}
__device__ __forceinline__ void applyDiag(float* sr, float* si, const float2* __restrict__ D) {
#pragma unroll
    for (int j = 0; j < 32; ++j) {
        float2 d = D[j];
        float a = sr[j], b = si[j];
        sr[j] = a * d.x - b * d.y;
        si[j] = a * d.y + b * d.x;
    }
}
__device__ __forceinline__ void crossBS(float* sr, float* si, float4 q, int h) {
    const float c = q.x, esi = q.z, c2 = q.w;
    const float e1 = h ? -q.y : q.y;
#pragma unroll
    for (int p = 0; p < 16; ++p) {
        float ar = h ? sr[p] : sr[p | 16];
        float ai = h ? si[p] : si[p | 16];
        float pr = __shfl_xor_sync(FULLMASK, ar, 1);
        float pi = __shfl_xor_sync(FULLMASK, ai, 1);
        float nr = c * ar + e1 * pr - esi * pi;
        float ni = c * ai + e1 * pi + esi * pr;
        if (h) { sr[p] = nr; si[p] = ni; sr[p | 16] *= c2; si[p | 16] *= c2; }
        else   { sr[p | 16] = nr; si[p | 16] = ni; }
    }
}
__device__ __forceinline__ void crossDisp(float* sr, float* si, float4 m, int h) {
    const float a = h ? m.w : m.x;
    const float b = h ? m.z : m.y;
#pragma unroll
    for (int j = 0; j < 32; ++j) {
        float pr = __shfl_xor_sync(FULLMASK, sr[j], 1);
        float pi = __shfl_xor_sync(FULLMASK, si[j], 1);
        sr[j] = a * sr[j] + b * pr;
        si[j] = a * si[j] + b * pi;
    }
}
__device__ __forceinline__ void apply_layer(float* sr, float* si,
                                            const float2* DA, const float2* DB,
                                            const float4* BS1, const float4* BS2,
                                            const float4* DSP, int h) {
    crossBS(sr, si, BS1[0], h);
    localBS<8>(sr, si, BS1[1]); localBS<4>(sr, si, BS1[2]);
    localBS<2>(sr, si, BS1[3]); localBS<1>(sr, si, BS1[4]);
    applyDiag(sr, si, DA + h * 32);
    crossBS(sr, si, BS2[0], h);
    localBS<8>(sr, si, BS2[1]); localBS<4>(sr, si, BS2[2]);
    localBS<2>(sr, si, BS2[3]); localBS<1>(sr, si, BS2[4]);
    applyDiag(sr, si, DB + h * 32);
    crossDisp(sr, si, DSP[0], h);
    localDisp<16>(sr, si, DSP[1]); localDisp<8>(sr, si, DSP[2]);
    localDisp<4 >(sr, si, DSP[3]); localDisp<2>(sr, si, DSP[4]);
    localDisp<1 >(sr, si, DSP[5]);
}

// ---------------- build W: push 64 basis vectors through var layers ----------------
extern "C" __global__ void __launch_bounds__(128)
build_w_kernel(const float* __restrict__ var)
{
    __shared__ float2 sDA[2][64];
    __shared__ float2 sDB[2][64];
    __shared__ float4 sBS1[2][5];
    __shared__ float4 sBS2[2][5];
    __shared__ float4 sDSP[2][6];
    const int tid = threadIdx.x;

    if (tid < 64) {
        const int j = tid;
        for (int l = 0; l < 2; ++l) {
            const float* v = var + 50 * l;
            float mag = 1.0f, phA = 0.0f, phB = 0.0f;
            for (int w = 0; w < 6; ++w) {
                int n = (j >> (5 - w)) & 1;
                float sh = fast_sech(v[16 + w]);
                float d0 = sqrtf(sh);
                mag *= n ? sh * d0 : d0;
                if (n) {
                    phA += v[10 + w] + (l ? var[44 + w] : 0.0f);
                    phB += v[32 + w];
                }
            }
            float s_, c_;
            __sincosf(phA, &s_, &c_); sDA[l][j] = make_float2(mag * c_, mag * s_);
            __sincosf(phB, &s_, &c_); sDB[l][j] = make_float2(c_, s_);
        }
    } else if (tid < 84) {
        int k = tid - 64;
        int isB2 = (k >= 10);
        if (isB2) k -= 10;
        int l = k / 5, i = k % 5;
        const float* v = var + 50 * l;
        float th, ph;
        if (isB2) { th = v[22 + 2 * i]; ph = v[23 + 2 * i]; }
        else {
            th = v[2 * i]; ph = v[2 * i + 1];
            if (l == 1) ph += var[44 + i] - var[44 + i + 1];
        }
        float st, ct, sp, cp;
        __sincosf(th, &st, &ct);
        __sincosf(ph, &sp, &cp);
        float4 q = make_float4(ct, st * cp, st * sp, 1.0f - 2.0f * st * st);
        if (isB2) sBS2[l][i] = q; else sBS1[l][i] = q;
    } else if (tid < 96) {
        int k = tid - 84;
        int l = k / 6, w = k % 6;
        float r = var[50 * l + 38 + w];
        float pf = __expf(-0.5f * r * r);
        sDSP[l][w] = make_float4(pf, -pf * r, pf * r, pf * (1.0f - r * r));
    }
    __syncthreads();

    const int t = tid >> 1, h = tid & 1;   // basis vector t, half h
    float sr[32], si[32];
#pragma unroll
    for (int j = 0; j < 32; ++j) { sr[j] = 0.0f; si[j] = 0.0f; }
    if ((t >> 5) == h) sr[t & 31] = 1.0f;

    apply_layer(sr, si, sDA[0], sDB[0], sBS1[0], sBS2[0], sDSP[0], h);
    apply_layer(sr, si, sDA[1], sDB[1], sBS1[1], sBS2[1], sDSP[1], h);

    // U[n,t] = sr[j]+i*si[j], n = h*32+j.  Interleaved real embedding:
    // M[2n]  [2t]=Re,  [2t+1]=-Im ;  M[2n+1][2t]=Im, [2t+1]=Re
#pragma unroll
    for (int j = 0; j < 32; ++j) {
        int n = h * 32 + j;
        Wg[(2 * n) * 128 + 2 * t]         =  sr[j];
        Wg[(2 * n) * 128 + 2 * t + 1]     = -si[j];
        Wg[(2 * n + 1) * 128 + 2 * t]     =  si[j];
        Wg[(2 * n + 1) * 128 + 2 * t + 1] =  sr[j];
    }
}

// ---------------- main kernel ----------------
// smem (bytes): [0:256) gamma, [256:512) beta, [512:1536) sSum[128][2],
//               [1536:2560) sSq[128][2], [2560:+34816) A, [37376:+34816) B
#define SM_GA 0
#define SM_BE 256
#define SM_SUM 512
#define SM_SQ 1536
#define SM_A 2560
#define SM_BT (2560 + 34816)
#define SMEM_TOTAL (SM_BT + 34816)
#define ROWB 272   // bytes per smem row (128 bf16 + 16B pad) -> conflict-free ldmatrix

__device__ __forceinline__ void wire_factors(const float* __restrict__ xp, int w,
                                             float& f0, float& f1r, float& f1i) {
    float r1 = xp[2 * w], dr = xp[28 + 2 * w], dphi = xp[29 + 2 * w];
    float kerr = xp[40 + w], r2 = xp[46 + 2 * w], rot2 = xp[58 + w];
    float sech1 = fast_sech(r1);
    float d01 = sqrtf(sech1);
    float pref = __expf(-0.5f * dr * dr);
    float sech2 = fast_sech(r2);
    float d02 = sqrtf(sech2);
    float d12 = sech2 * d02;
    float base = d01 * pref;
    f0 = base * d02;
    float A = base * d12 * dr;
    float sA, cA;
    __sincosf(dphi + kerr + rot2, &sA, &cA);
    f1r = A * cA; f1i = A * sA;
}
template<int W>   // wires 1..4 over 16-entry half-expansion
__device__ __forceinline__ void expandH(float* gr, float* gi, float f0, float f1r, float f1i) {
    const int M = 1 << (4 - W);
#pragma unroll
    for (int t = 0; t < (1 << (W - 1)); ++t) {
        const int j = t << (5 - W);
        float a = gr[j], b = gi[j];
        gr[j | M] = a * f1r - b * f1i;
        gi[j | M] = a * f1i + b * f1r;
        gr[j] = a * f0;
        gi[j] = b * f0;
    }
}

extern "C" __global__ void __launch_bounds__(256)
ffblock_hmma_kernel(const float* __restrict__ x, const float* __restrict__ gamma,
                    const float* __restrict__ beta, float* __restrict__ out, int nsamp)
{
    extern __shared__ char smem[];
    float* smf = (float*)smem;
    const uint32_t sbase = smem_u32(smem);
    const int tid = threadIdx.x;
    const int wid = tid >> 5;
    const int lane = tid & 31;

    if (tid < 64) {
        smf[SM_GA / 4 + tid] = gamma[tid];
        smf[SM_BE / 4 + tid] = beta[tid];
    }

    // ---- F build: 2 threads per sample row; thread h handles j = 16h..16h+15 ----
    {
        const int row = tid >> 1, h = tid & 1;
        int s = blockIdx.x * 128 + row;
        if (s >= nsamp) s = nsamp - 1;
        const float* xp = x + (size_t)s * 64;

        float gr[16], gi[16];
        float f0, f1r, f1i;
        wire_factors(xp, 0, f0, f1r, f1i);
        gr[0] = h ? f1r : f0;
        gi[0] = h ? f1i : 0.0f;
        wire_factors(xp, 1, f0, f1r, f1i); expandH<1>(gr, gi, f0, f1r, f1i);
        wire_factors(xp, 2, f0, f1r, f1i); expandH<2>(gr, gi, f0, f1r, f1i);
        wire_factors(xp, 3, f0, f1r, f1i); expandH<3>(gr, gi, f0, f1r, f1i);
        wire_factors(xp, 4, f0, f1r, f1i); expandH<4>(gr, gi, f0, f1r, f1i);
        float f50, f51r, f51i;
        wire_factors(xp, 5, f50, f51r, f51i);

        char* rowp = smem + SM_A + row * ROWB + h * 128;  // 16 j's -> 128 bytes
#pragma unroll
        for (int jj = 0; jj < 16; ++jj) {
            // t0 = 2*j_global (n5=0): (Re,Im);  t1 = 2*j_global+1 (n5=1): (Re,Im)
            float re0 = gr[jj] * f50;
            float im0 = gi[jj] * f50;
            float re1 = gr[jj] * f51r - gi[jj] * f51i;
            float im1 = gr[jj] * f51i + gi[jj] * f51r;
            __nv_bfloat162 w0 = __floats2bfloat162_rn(re0, im0);
            __nv_bfloat162 w1 = __floats2bfloat162_rn(re1, im1);
            uint2 pk = make_uint2(*(uint32_t*)&w0, *(uint32_t*)&w1);
            *(uint2*)(rowp + jj * 8) = pk;
        }
    }

    // ---- B fill: M rows (c = 0..127), k-contiguous bf16 ----
    {
        const float2* wsrc = (const float2*)Wg;
#pragma unroll
        for (int it = 0; it < 32; ++it) {
            int i = it * 256 + tid;          // 8192 float2 total
            int c = i >> 6, kp = i & 63;
            float2 w2 = wsrc[i];
            __nv_bfloat162 wb = __floats2bfloat162_rn(w2.x, w2.y);
            *(uint32_t*)(smem + SM_BT + c * ROWB + kp * 4) = *(uint32_t*)&wb;
        }
    }
    __syncthreads();

    // ---- HMMA GEMM: warp (warpM, warpN) -> samples 32*warpM.., cols 64*warpN.. ----
    const int warpM = wid >> 1, warpN = wid & 1;
    const uint32_t aAddr = sbase + SM_A +
        (uint32_t)(warpM * 32 + (lane & 15)) * ROWB + (uint32_t)(lane >> 4) * 16;
    const int grp = lane >> 3;
    const uint32_t bAddr = sbase + SM_BT +
        (uint32_t)(warpN * 64 + (grp >> 1) * 8 + (lane & 7)) * ROWB + (uint32_t)(grp & 1) * 16;

    float acc[2][8][4];
#pragma unroll
    for (int a = 0; a < 2; ++a)
#pragma unroll
        for (int b = 0; b < 8; ++b)
#pragma unroll
            for (int c = 0; c < 4; ++c) acc[a][b][c] = 0.0f;

#pragma unroll
    for (int kt = 0; kt < 8; ++kt) {
        uint32_t a0[4], a1[4];
        ldsm4(a0, aAddr + kt * 32);
        ldsm4(a1, aAddr + 16 * ROWB + kt * 32);
#pragma unroll
        for (int bt = 0; bt < 4; ++bt) {
            uint32_t bb[4];
            ldsm4(bb, bAddr + bt * 16 * ROWB + kt * 32);
            mma16816(acc[0][2 * bt],     a0, bb);
            mma16816(acc[1][2 * bt],     a1, bb);
            mma16816(acc[0][2 * bt + 1], a0, bb + 2);
            mma16816(acc[1][2 * bt + 1], a1, bb + 2);
        }
    }

    // ---- epilogue: probs + residual, LN partials ----
    const int g = lane >> 2, lam = lane & 3;
    const int s0 = blockIdx.x * 128;
    float* sSum = smf + SM_SUM / 4;
    float* sSq  = smf + SM_SQ / 4;

#pragma unroll
    for (int mt = 0; mt < 2; ++mt) {
#pragma unroll
        for (int hi = 0; hi < 2; ++hi) {
            int row = warpM * 32 + mt * 16 + hi * 8 + g;
            int srow = s0 + row; if (srow >= nsamp) srow = nsamp - 1;
            float sum = 0.0f, sq = 0.0f;
#pragma unroll
            for (int nt = 0; nt < 8; ++nt) {
                float re = acc[mt][nt][2 * hi], im = acc[mt][nt][2 * hi + 1];
                int n = warpN * 32 + nt * 4 + lam;
                float xv = x[(size_t)srow * 64 + n];
                float yy = re * re + im * im + xv;
                acc[mt][nt][2 * hi] = yy;
                sum += yy; sq += yy * yy;
            }
            sum += __shfl_xor_sync(FULLMASK, sum, 1);
            sum += __shfl_xor_sync(FULLMASK, sum, 2);
            sq  += __shfl_xor_sync(FULLMASK, sq, 1);
            sq  += __shfl_xor_sync(FULLMASK, sq, 2);
            if (lam == 0) {
                sSum[row * 2 + warpN] = sum;
                sSq[row * 2 + warpN]  = sq;
            }
        }
    }
    __syncthreads();

    // ---- normalize + store ----
#pragma unroll
    for (int mt = 0; mt < 2; ++mt) {
#pragma unroll
        for (int hi = 0; hi < 2; ++hi) {
            int row = warpM * 32 + mt * 16 + hi * 8 + g;
            float sum = sSum[row * 2] + sSum[row * 2 + 1];
            float sq  = sSq[row * 2] + sSq[row * 2 + 1];
            float mean = sum * (1.0f / 64.0f);
            float varr = sq * (1.0f / 64.0f) - mean * mean;
            float inv = rsqrtf(varr + 1e-5f);
            if (s0 + row < nsamp) {
                float* op = out + (size_t)(s0 + row) * 64;
#pragma unroll
                for (int nt = 0; nt < 8; ++nt) {
                    int n = warpN * 32 + nt * 4 + lam;
                    float yv = acc[mt][nt][2 * hi];
                    op[n] = (yv - mean) * inv * smf[SM_GA / 4 + n] + smf[SM_BE / 4 + n];
                }
            }
        }
    }
}

extern "C" void kernel_launch(void* const* d_in, const int* in_sizes, int n_in,
                              void* d_out, int out_size) {
    const float* x     = (const float*)d_in[0];
    const float* var   = (const float*)d_in[1];
    const float* gamma = (const float*)d_in[2];
    const float* beta  = (const float*)d_in[3];
    float* out = (float*)d_out;

    int nsamp = in_sizes[0] / 64;
    int tiles = (nsamp + 127) / 128;

    cudaFuncSetAttribute(ffblock_hmma_kernel,
                         cudaFuncAttributeMaxDynamicSharedMemorySize, SMEM_TOTAL);

    build_w_kernel<<<1, 128>>>(var);
    ffblock_hmma_kernel<<<tiles, 256, SMEM_TOTAL>>>(x, gamma, beta, out, nsamp);
}

// round 17
// speedup vs baseline: 2.9691x; 1.3874x over previous
#include <cuda_runtime.h>
#include <cuda_bf16.h>
#include <cstdint>

#define FULLMASK 0xFFFFFFFFu

// Variational map, bf16, pre-packed: word (c*64 + t) = bf16x2 {k=2t, k=2t+1} of row c.
// Interleaved real embedding: row 2n = Re-part row, row 2n+1 = Im-part row.
__device__ uint32_t Wb[8192];

// ---------------- tensor-core helpers (compute_103-legal, sm_80 baseline) ----------------
__device__ __forceinline__ uint32_t smem_u32(const void* p) {
    uint32_t a;
    asm("{ .reg .u64 t; cvta.to.shared.u64 t, %1; cvt.u32.u64 %0, t; }" : "=r"(a) : "l"(p));
    return a;
}
__device__ __forceinline__ void ldsm4(uint32_t* r, uint32_t addr) {
    asm volatile("ldmatrix.sync.aligned.m8n8.x4.shared.b16 {%0,%1,%2,%3}, [%4];"
                 : "=r"(r[0]), "=r"(r[1]), "=r"(r[2]), "=r"(r[3]) : "r"(addr));
}
__device__ __forceinline__ void mma16816(float* d, const uint32_t* a, const uint32_t* b) {
    asm volatile("mma.sync.aligned.m16n8k16.row.col.f32.bf16.bf16.f32 "
                 "{%0,%1,%2,%3}, {%4,%5,%6,%7}, {%8,%9}, {%0,%1,%2,%3};"
                 : "+f"(d[0]), "+f"(d[1]), "+f"(d[2]), "+f"(d[3])
                 : "r"(a[0]), "r"(a[1]), "r"(a[2]), "r"(a[3]), "r"(b[0]), "r"(b[1]));
}

// ---------------- gate math (build_w only; proven) ----------------
__device__ __forceinline__ float fast_sech(float r) {
    float e = __expf(r);
    return __fdividef(2.0f, e + __fdividef(1.0f, e));
}
template<int LO>
__device__ __forceinline__ void localBS(float* sr, float* si, float4 q) {
    const float c = q.x, esr = q.y, esi = q.z, c2 = q.w;
    const int HI = LO << 1;
#pragma unroll
    for (int p = 0; p < 8; ++p) {
        const int j00 = ((p & ~(LO - 1)) << 2) | (p & (LO - 1));
        const int j01 = j00 | LO, j10 = j00 | HI, j11 = j00 | HI | LO;
        float a01 = sr[j01], b01 = si[j01], a10 = sr[j10], b10 = si[j10];
        sr[j01] = c * a01 + esr * a10 - esi * b10;
        si[j01] = c * b01 + esr * b10 + esi * a10;
        sr[j10] = c * a10 - esr * a01 - esi * b01;
        si[j10] = c * b10 - esr * b01 + esi * a01;
        sr[j11] *= c2; si[j11] *= c2;
    }
}
template<int M>
__device__ __forceinline__ void localDisp(float* sr, float* si, float4 m) {
#pragma unroll
    for (int p = 0; p < 16; ++p) {
        const int j0 = ((p & ~(M - 1)) << 1) | (p & (M - 1));
        const int j1 = j0 | M;
        float a0 = sr[j0], b0 = si[j0], a1 = sr[j1], b1 = si[j1];
        sr[j0] = m.x * a0 + m.y * a1;  si[j0] = m.x * b0 + m.y * b1;
        sr[j1] = m.z * a0 + m.w * a1;  si[j1] = m.z * b0 + m.w * b1;
    }
}
__device__ __forceinline__ void applyDiag(float* sr, float* si, const float2* __restrict__ D) {
#pragma unroll
    for (int j = 0; j < 32; ++j) {
        float2 d = D[j];
        float a = sr[j], b = si[j];
        sr[j] = a * d.x - b * d.y;
        si[j] = a * d.y + b * d.x;
    }
}
__device__ __forceinline__ void crossBS(float* sr, float* si, float4 q, int h) {
    const float c = q.x, esi = q.z, c2 = q.w;
    const float e1 = h ? -q.y : q.y;
#pragma unroll
    for (int p = 0; p < 16; ++p) {
        float ar = h ? sr[p] : sr[p | 16];
        float ai = h ? si[p] : si[p | 16];
        float pr = __shfl_xor_sync(FULLMASK, ar, 1);
        float pi = __shfl_xor_sync(FULLMASK, ai, 1);
        float nr = c * ar + e1 * pr - esi * pi;
        float ni = c * ai + e1 * pi + esi * pr;
        if (h) { sr[p] = nr; si[p] = ni; sr[p | 16] *= c2; si[p | 16] *= c2; }
        else   { sr[p | 16] = nr; si[p | 16] = ni; }
    }
}
__device__ __forceinline__ void crossDisp(float* sr, float* si, float4 m, int h) {
    const float a = h ? m.w : m.x;
    const float b = h ? m.z : m.y;
#pragma unroll
    for (int j = 0; j < 32; ++j) {
        float pr = __shfl_xor_sync(FULLMASK, sr[j], 1);
        float pi = __shfl_xor_sync(FULLMASK, si[j], 1);
        sr[j] = a * sr[j] + b * pr;
        si[j] = a * si[j] + b * pi;
    }
}
__device__ __forceinline__ void apply_layer(float* sr, float* si,
                                            const float2* DA, const float2* DB,
                                            const float4* BS1, const float4* BS2,
                                            const float4* DSP, int h) {
    crossBS(sr, si, BS1[0], h);
    localBS<8>(sr, si, BS1[1]); localBS<4>(sr, si, BS1[2]);
    localBS<2>(sr, si, BS1[3]); localBS<1>(sr, si, BS1[4]);
    applyDiag(sr, si, DA + h * 32);
    crossBS(sr, si, BS2[0], h);
    localBS<8>(sr, si, BS2[1]); localBS<4>(sr, si, BS2[2]);
    localBS<2>(sr, si, BS2[3]); localBS<1>(sr, si, BS2[4]);
    applyDiag(sr, si, DB + h * 32);
    crossDisp(sr, si, DSP[0], h);
    localDisp<16>(sr, si, DSP[1]); localDisp<8>(sr, si, DSP[2]);
    localDisp<4 >(sr, si, DSP[3]); localDisp<2>(sr, si, DSP[4]);
    localDisp<1 >(sr, si, DSP[5]);
}

// ---------------- build W (bf16, pre-packed words) ----------------
extern "C" __global__ void __launch_bounds__(128)
build_w_kernel(const float* __restrict__ var)
{
    __shared__ float2 sDA[2][64];
    __shared__ float2 sDB[2][64];
    __shared__ float4 sBS1[2][5];
    __shared__ float4 sBS2[2][5];
    __shared__ float4 sDSP[2][6];
    const int tid = threadIdx.x;

    if (tid < 64) {
        const int j = tid;
        for (int l = 0; l < 2; ++l) {
            const float* v = var + 50 * l;
            float mag = 1.0f, phA = 0.0f, phB = 0.0f;
            for (int w = 0; w < 6; ++w) {
                int n = (j >> (5 - w)) & 1;
                float sh = fast_sech(v[16 + w]);
                float d0 = sqrtf(sh);
                mag *= n ? sh * d0 : d0;
                if (n) {
                    phA += v[10 + w] + (l ? var[44 + w] : 0.0f);
                    phB += v[32 + w];
                }
            }
            float s_, c_;
            __sincosf(phA, &s_, &c_); sDA[l][j] = make_float2(mag * c_, mag * s_);
            __sincosf(phB, &s_, &c_); sDB[l][j] = make_float2(c_, s_);
        }
    } else if (tid < 84) {
        int k = tid - 64;
        int isB2 = (k >= 10);
        if (isB2) k -= 10;
        int l = k / 5, i = k % 5;
        const float* v = var + 50 * l;
        float th, ph;
        if (isB2) { th = v[22 + 2 * i]; ph = v[23 + 2 * i]; }
        else {
            th = v[2 * i]; ph = v[2 * i + 1];
            if (l == 1) ph += var[44 + i] - var[44 + i + 1];
        }
        float st, ct, sp, cp;
        __sincosf(th, &st, &ct);
        __sincosf(ph, &sp, &cp);
        float4 q = make_float4(ct, st * cp, st * sp, 1.0f - 2.0f * st * st);
        if (isB2) sBS2[l][i] = q; else sBS1[l][i] = q;
    } else if (tid < 96) {
        int k = tid - 84;
        int l = k / 6, w = k % 6;
        float r = var[50 * l + 38 + w];
        float pf = __expf(-0.5f * r * r);
        sDSP[l][w] = make_float4(pf, -pf * r, pf * r, pf * (1.0f - r * r));
    }
    __syncthreads();

    const int t = tid >> 1, h = tid & 1;   // basis vector t, half h
    float sr[32], si[32];
#pragma unroll
    for (int j = 0; j < 32; ++j) { sr[j] = 0.0f; si[j] = 0.0f; }
    if ((t >> 5) == h) sr[t & 31] = 1.0f;

    apply_layer(sr, si, sDA[0], sDB[0], sBS1[0], sBS2[0], sDSP[0], h);
    apply_layer(sr, si, sDA[1], sDB[1], sBS1[1], sBS2[1], sDSP[1], h);

    // U[n,t] = sr[j]+i*si[j], n = h*32+j.
    // Row 2n word t = (Re, -Im); row 2n+1 word t = (Im, Re). (low half = k=2t)
#pragma unroll
    for (int j = 0; j < 32; ++j) {
        int n = h * 32 + j;
        __nv_bfloat162 wre = __floats2bfloat162_rn(sr[j], -si[j]);
        __nv_bfloat162 wim = __floats2bfloat162_rn(si[j],  sr[j]);
        Wb[(2 * n) * 64 + t]     = *(uint32_t*)&wre;
        Wb[(2 * n + 1) * 64 + t] = *(uint32_t*)&wim;
    }
}

// ---------------- main kernel ----------------
// smem: [0:256) gamma, [256:512) beta, [512:1536) sSum[128][2], [1536:2560) sSq[128][2],
//       [2560:+34816) X stage (128 rows x 272B), then A tile, then B tile.
#define SM_GA 0
#define SM_BE 256
#define SM_SUM 512
#define SM_SQ 1536
#define SM_X 2560
#define SM_A (SM_X + 34816)
#define SM_BT (SM_A + 34816)
#define SMEM_TOTAL (SM_BT + 34816)
#define ROWB 272   // 68 words per row: 68 mod 32 = 4 -> conflict-free ldmatrix/LDS patterns

__device__ __forceinline__ void wire_factors(const float* xp, int w,
                                             float& f0, float& f1r, float& f1i) {
    float r1 = xp[2 * w], dr = xp[28 + 2 * w], dphi = xp[29 + 2 * w];
    float kerr = xp[40 + w], r2 = xp[46 + 2 * w], rot2 = xp[58 + w];
    float sech1 = fast_sech(r1);
    float d01 = sqrtf(sech1);
    float pref = __expf(-0.5f * dr * dr);
    float sech2 = fast_sech(r2);
    float d02 = sqrtf(sech2);
    float d12 = sech2 * d02;
    float base = d01 * pref;
    f0 = base * d02;
    float A = base * d12 * dr;
    float sA, cA;
    __sincosf(dphi + kerr + rot2, &sA, &cA);
    f1r = A * cA; f1i = A * sA;
}
template<int W>   // wires 1..4 over 16-entry half-expansion
__device__ __forceinline__ void expandH(float* gr, float* gi, float f0, float f1r, float f1i) {
    const int M = 1 << (4 - W);
#pragma unroll
    for (int t = 0; t < (1 << (W - 1)); ++t) {
        const int j = t << (5 - W);
        float a = gr[j], b = gi[j];
        gr[j | M] = a * f1r - b * f1i;
        gi[j | M] = a * f1i + b * f1r;
        gr[j] = a * f0;
        gi[j] = b * f0;
    }
}

extern "C" __global__ void __launch_bounds__(256)
ffblock_hmma_kernel(const float* __restrict__ x, const float* __restrict__ gamma,
                    const float* __restrict__ beta, float* __restrict__ out, int nsamp)
{
    extern __shared__ char smem[];
    float* smf = (float*)smem;
    const uint32_t sbase = smem_u32(smem);
    const int tid = threadIdx.x;
    const int wid = tid >> 5;
    const int lane = tid & 31;

    if (tid < 64) {
        smf[SM_GA / 4 + tid] = gamma[tid];
        smf[SM_BE / 4 + tid] = beta[tid];
    }

    // ---- stage x tile into smem, coalesced float4 ----
    {
        const float4* x4 = (const float4*)x;
        const long maxi = (long)nsamp * 16 - 1;
#pragma unroll
        for (int it = 0; it < 8; ++it) {
            int j = it * 256 + tid;                 // 0..2047
            long gi_ = (long)blockIdx.x * 2048 + j;
            if (gi_ > maxi) gi_ = maxi;
            float4 v = x4[gi_];
            int r = j >> 4, c4 = j & 15;
            *(float4*)&smf[SM_X / 4 + r * 68 + c4 * 4] = v;
        }
    }
    // ---- B fill: plain uint4 copy of pre-packed bf16 W ----
    {
        const uint4* wb4 = (const uint4*)Wb;
#pragma unroll
        for (int it = 0; it < 8; ++it) {
            int j = it * 256 + tid;                 // 0..2047
            int c = j >> 4, kq = j & 15;
            *(uint4*)(smem + SM_BT + c * ROWB + kq * 16) = wb4[j];
        }
    }
    __syncthreads();

    // ---- F build from smem x: 2 threads per sample row ----
    {
        const int row = tid >> 1, h = tid & 1;
        const float* xp = &smf[SM_X / 4 + row * 68];

        float gr[16], gi[16];
        float f0, f1r, f1i;
        wire_factors(xp, 0, f0, f1r, f1i);
        gr[0] = h ? f1r : f0;
        gi[0] = h ? f1i : 0.0f;
        wire_factors(xp, 1, f0, f1r, f1i); expandH<1>(gr, gi, f0, f1r, f1i);
        wire_factors(xp, 2, f0, f1r, f1i); expandH<2>(gr, gi, f0, f1r, f1i);
        wire_factors(xp, 3, f0, f1r, f1i); expandH<3>(gr, gi, f0, f1r, f1i);
        wire_factors(xp, 4, f0, f1r, f1i); expandH<4>(gr, gi, f0, f1r, f1i);
        float f50, f51r, f51i;
        wire_factors(xp, 5, f50, f51r, f51i);

        char* rowp = smem + SM_A + row * ROWB + h * 128;
#pragma unroll
        for (int jj = 0; jj < 16; ++jj) {
            float re0 = gr[jj] * f50;
            float im0 = gi[jj] * f50;
            float re1 = gr[jj] * f51r - gi[jj] * f51i;
            float im1 = gr[jj] * f51i + gi[jj] * f51r;
            __nv_bfloat162 w0 = __floats2bfloat162_rn(re0, im0);
            __nv_bfloat162 w1 = __floats2bfloat162_rn(re1, im1);
            uint2 pk = make_uint2(*(uint32_t*)&w0, *(uint32_t*)&w1);
            *(uint2*)(rowp + jj * 8) = pk;
        }
    }
    __syncthreads();

    // ---- HMMA GEMM: warp (warpM, warpN) -> rows 32*warpM.., cols 64*warpN.. ----
    const int warpM = wid >> 1, warpN = wid & 1;
    const uint32_t aAddr = sbase + SM_A +
        (uint32_t)(warpM * 32 + (lane & 15)) * ROWB + (uint32_t)(lane >> 4) * 16;
    const int grp = lane >> 3;
    const uint32_t bAddr = sbase + SM_BT +
        (uint32_t)(warpN * 64 + (grp >> 1) * 8 + (lane & 7)) * ROWB + (uint32_t)(grp & 1) * 16;

    float acc[2][8][4];
#pragma unroll
    for (int a = 0; a < 2; ++a)
#pragma unroll
        for (int b = 0; b < 8; ++b)
#pragma unroll
            for (int c = 0; c < 4; ++c) acc[a][b][c] = 0.0f;

#pragma unroll
    for (int kt = 0; kt < 8; ++kt) {
        uint32_t a0[4], a1[4];
        ldsm4(a0, aAddr + kt * 32);
        ldsm4(a1, aAddr + 16 * ROWB + kt * 32);
#pragma unroll
        for (int bt = 0; bt < 4; ++bt) {
            uint32_t bb[4];
            ldsm4(bb, bAddr + bt * 16 * ROWB + kt * 32);
            mma16816(acc[0][2 * bt],     a0, bb);
            mma16816(acc[1][2 * bt],     a1, bb);
            mma16816(acc[0][2 * bt + 1], a0, bb + 2);
            mma16816(acc[1][2 * bt + 1], a1, bb + 2);
        }
    }

    // ---- epilogue phase 1: probs + residual into x-smem (in place), LN partials ----
    const int g = lane >> 2, lam = lane & 3;
    float* sSum = smf + SM_SUM / 4;
    float* sSq  = smf + SM_SQ / 4;

#pragma unroll
    for (int mt = 0; mt < 2; ++mt) {
#pragma unroll
        for (int hi = 0; hi < 2; ++hi) {
            int row = warpM * 32 + mt * 16 + hi * 8 + g;
            float sum = 0.0f, sq = 0.0f;
#pragma unroll
            for (int nt = 0; nt < 8; ++nt) {
                float re = acc[mt][nt][2 * hi], im = acc[mt][nt][2 * hi + 1];
                int n = warpN * 32 + nt * 4 + lam;
                int w = SM_X / 4 + row * 68 + n;
                float yy = re * re + im * im + smf[w];
                smf[w] = yy;
                sum += yy; sq += yy * yy;
            }
            sum += __shfl_xor_sync(FULLMASK, sum, 1);
            sum += __shfl_xor_sync(FULLMASK, sum, 2);
            sq  += __shfl_xor_sync(FULLMASK, sq, 1);
            sq  += __shfl_xor_sync(FULLMASK, sq, 2);
            if (lam == 0) {
                sSum[row * 2 + warpN] = sum;
                sSq[row * 2 + warpN]  = sq;
            }
        }
    }
    __syncthreads();

    // ---- phase 2: normalize + fully-coalesced float4 stores ----
    {
        float4* out4 = (float4*)out;
        const long maxo = (long)nsamp * 16;
#pragma unroll
        for (int it = 0; it < 8; ++it) {
            int j = it * 256 + tid;                 // 0..2047
            int r = j >> 4, c4 = j & 15;
            float sum = sSum[r * 2] + sSum[r * 2 + 1];
            float sq  = sSq[r * 2] + sSq[r * 2 + 1];
            float mean = sum * (1.0f / 64.0f);
            float varr = sq * (1.0f / 64.0f) - mean * mean;
            float inv = rsqrtf(varr + 1e-5f);
            float4 yv = *(float4*)&smf[SM_X / 4 + r * 68 + c4 * 4];
            float4 ga = *(float4*)&smf[SM_GA / 4 + c4 * 4];
            float4 be = *(float4*)&smf[SM_BE / 4 + c4 * 4];
            float4 ov;
            ov.x = (yv.x - mean) * inv * ga.x + be.x;
            ov.y = (yv.y - mean) * inv * ga.y + be.y;
            ov.z = (yv.z - mean) * inv * ga.z + be.z;
            ov.w = (yv.w - mean) * inv * ga.w + be.w;
            long go = (long)blockIdx.x * 2048 + j;
            if (go < maxo) out4[go] = ov;
        }
    }
}

extern "C" void kernel_launch(void* const* d_in, const int* in_sizes, int n_in,
                              void* d_out, int out_size) {
    const float* x     = (const float*)d_in[0];
    const float* var   = (const float*)d_in[1];
    const float* gamma = (const float*)d_in[2];
    const float* beta  = (const float*)d_in[3];
    float* out = (float*)d_out;

    int nsamp = in_sizes[0] / 64;
    int tiles = (nsamp + 127) / 128;

    cudaFuncSetAttribute(ffblock_hmma_kernel,
                         cudaFuncAttributeMaxDynamicSharedMemorySize, SMEM_TOTAL);

    build_w_kernel<<<1, 128>>>(var);
    ffblock_hmma_kernel<<<tiles, 256, SMEM_TOTAL>>>(x, gamma, beta, out, nsamp);
}